// round 1
// baseline (speedup 1.0000x reference)
#include <cuda_runtime.h>
#include <math.h>

#define NN     32
#define TIN    12
#define HID    64
#define HEADS  8
#define HH     512
#define EPB    256
#define ET     288
#define E_     131072
#define NTH    256
#define H1S    520   // padded stride for h1 rows (8 heads * 65)
#define HS     65    // padded 64-wide row stride
#define XIS    193   // padded 192-wide row stride
#define YSS    65

// shared memory offsets (in floats)
#define O_H1   0        // 32*520 = 16640   (GAT phase)   | GRU: xi (64*193) + ys (64*65)
#define O_XI   0
#define O_YS   12352
#define O_X    16640    // 384
#define O_ES   17024    // 256
#define O_ED   17280    // 256
#define O_E    17536    // 2304 (288*8) e-scores -> p
#define O_SRC  19840    // 288 (int)
#define O_DST  20128    // 288 (int)
#define O_CNT  20416    // 32  (int)
#define O_OFF  20448    // 33  (int)
#define O_SLOT 20481    // 288 (int)
#define O_CSR  20769    // 288 (int)
#define O_H2   21057    // 32*65 = 2080
#define O_G2   23137    // 32*65 = 2080 (GAT2 out -> LN -> hln)
#define O_ES2  25217    // 32
#define O_ED2  25249    // 32
#define O_E2   25281    // 288
#define O_M2   25569    // 32
#define O_IS2  25601    // 32
#define O_AL2  25633    // 288
#define O_HSM  25921    // 64 (GRU hidden)
#define O_GH   25985    // 192
#define SMEM_FLOATS 26177   // 104708 bytes -> 2 CTAs/SM

__device__ __forceinline__ float sigmf_(float x){ return 1.0f/(1.0f+expf(-x)); }
__device__ __forceinline__ float eluf_(float x){ return x>0.f ? x : expm1f(x); }
__device__ __forceinline__ float lreluf_(float x){ return x>0.f ? x : 0.2f*x; }

__global__ void __launch_bounds__(NTH, 2) fused_gatgru_kernel(
    const float* __restrict__ x,   const int*   __restrict__ ei,
    const float* __restrict__ W1,  const float* __restrict__ aS1,
    const float* __restrict__ aD1, const float* __restrict__ b1,
    const float* __restrict__ W2,  const float* __restrict__ aS2,
    const float* __restrict__ aD2, const float* __restrict__ b2,
    const float* __restrict__ gamma, const float* __restrict__ beta,
    const float* __restrict__ Wi1, const float* __restrict__ Wh1,
    const float* __restrict__ bi1, const float* __restrict__ bh1,
    const float* __restrict__ Wi2, const float* __restrict__ Wh2,
    const float* __restrict__ bi2, const float* __restrict__ bh2,
    const float* __restrict__ Wf,  const float* __restrict__ bf,
    float* __restrict__ out)
{
    extern __shared__ float sm[];
    int* smi = (int*)sm;
    const int tid = threadIdx.x;
    const int b   = blockIdx.x;

    // ---------------- Phase 0: load x tile + local edge list, zero counters
    for (int i = tid; i < NN*TIN; i += NTH) sm[O_X + i] = x[b*NN*TIN + i];
    for (int k = tid; k < ET; k += NTH) {
        int s, d;
        if (k < EPB) { s = ei[b*EPB + k] - b*NN; d = ei[E_ + b*EPB + k] - b*NN; }
        else         { s = d = k - EPB; }      // self loops appended last
        smi[O_SRC + k] = s; smi[O_DST + k] = d;
    }
    if (tid < NN) smi[O_CNT + tid] = 0;
    __syncthreads();

    // ---------------- Phase 1: h1 = x @ W1  (32 x 512, padded) + CSR counting
    for (int jj = 0; jj < 2; jj++) {
        int j = tid + jj*NTH;
        float w[TIN];
        #pragma unroll
        for (int k = 0; k < TIN; k++) w[k] = W1[k*HH + j];
        int ho = (j >> 6)*HS + (j & 63);
        for (int n = 0; n < NN; n++) {
            float acc = 0.f;
            #pragma unroll
            for (int k = 0; k < TIN; k++) acc = fmaf(sm[O_X + n*TIN + k], w[k], acc);
            sm[O_H1 + n*H1S + ho] = acc;
        }
    }
    for (int k = tid; k < ET; k += NTH)
        smi[O_SLOT + k] = atomicAdd(&smi[O_CNT + smi[O_DST + k]], 1);
    __syncthreads();

    // ---------------- Phase 2: es/ed dots + CSR prefix sum
    {
        int n = tid >> 3, h = tid & 7;
        const float* hr = &sm[O_H1 + n*H1S + h*HS];
        float es = 0.f, ed = 0.f;
        #pragma unroll
        for (int c = 0; c < HID; c++) {
            float v = hr[c];
            es = fmaf(v, aS1[h*HID + c], es);
            ed = fmaf(v, aD1[h*HID + c], ed);
        }
        sm[O_ES + n*8 + h] = es; sm[O_ED + n*8 + h] = ed;
    }
    if (tid == 0) {
        int acc = 0;
        for (int d = 0; d < NN; d++) { smi[O_OFF + d] = acc; acc += smi[O_CNT + d]; }
        smi[O_OFF + NN] = acc;
    }
    __syncthreads();

    // ---------------- Phase 3: edge scores + CSR scatter
    for (int idx = tid; idx < ET*HEADS; idx += NTH) {
        int k = idx >> 3, h = idx & 7;
        float e = sm[O_ES + smi[O_SRC + k]*8 + h] + sm[O_ED + smi[O_DST + k]*8 + h];
        sm[O_E + idx] = lreluf_(e);
    }
    for (int k = tid; k < ET; k += NTH)
        smi[O_CSR + smi[O_OFF + smi[O_DST + k]] + smi[O_SLOT + k]] = k;
    __syncthreads();

    // ---------------- Phase 4: GAT1 per-dst softmax + aggregation (thread = dst,head)
    {
        int dst = tid >> 3, h = tid & 7;
        int o   = smi[O_OFF + dst], deg = smi[O_OFF + dst + 1] - o;
        float m = -1e30f;
        for (int i = 0; i < deg; i++)
            m = fmaxf(m, sm[O_E + smi[O_CSR + o + i]*8 + h]);
        float s = 0.f;
        for (int i = 0; i < deg; i++) {
            int k = smi[O_CSR + o + i];
            float p = expf(sm[O_E + k*8 + h] - m);
            sm[O_E + k*8 + h] = p;
            s += p;
        }
        float inv = 1.f/(s + 1e-16f);
        float acc[HID];
        #pragma unroll
        for (int c = 0; c < HID; c++) acc[c] = 0.f;
        for (int i = 0; i < deg; i++) {
            int k = smi[O_CSR + o + i];
            float p = sm[O_E + k*8 + h];
            const float* hr = &sm[O_H1 + smi[O_SRC + k]*H1S + h*HS];
            #pragma unroll
            for (int c = 0; c < HID; c++) acc[c] = fmaf(p, hr[c], acc[c]);
        }
        __syncthreads();   // all reads of h1 complete before in-place overwrite
        float* orow = &sm[O_H1 + dst*H1S + h*HS];
        #pragma unroll
        for (int c = 0; c < HID; c++)
            orow[c] = eluf_(fmaf(acc[c], inv, b1[h*HID + c]));
    }
    __syncthreads();

    // ---------------- Phase 5: h2 = out1 @ W2   (32 x 64)
    {
        int c = tid & 63, grp = tid >> 6;   // 4 groups of 8 nodes
        float acc[8];
        #pragma unroll
        for (int i = 0; i < 8; i++) acc[i] = 0.f;
        #pragma unroll 4
        for (int k = 0; k < HH; k++) {
            float w = W2[k*HID + c];
            int off = O_H1 + (k >> 6)*HS + (k & 63);
            #pragma unroll
            for (int i = 0; i < 8; i++)
                acc[i] = fmaf(sm[off + (grp*8 + i)*H1S], w, acc[i]);
        }
        #pragma unroll
        for (int i = 0; i < 8; i++) sm[O_H2 + (grp*8 + i)*HS + c] = acc[i];
    }
    __syncthreads();

    // ---------------- Phase 6: GAT2 attention
    if (tid < 64) {
        int n = tid & 31;
        const float* a  = (tid < 32) ? aS2 : aD2;
        const float* hr = &sm[O_H2 + n*HS];
        float v = 0.f;
        #pragma unroll
        for (int c = 0; c < HID; c++) v = fmaf(hr[c], a[c], v);
        sm[(tid < 32 ? O_ES2 : O_ED2) + n] = v;
    }
    __syncthreads();
    for (int k = tid; k < ET; k += NTH)
        sm[O_E2 + k] = lreluf_(sm[O_ES2 + smi[O_SRC + k]] + sm[O_ED2 + smi[O_DST + k]]);
    __syncthreads();
    if (tid < NN) {
        int o = smi[O_OFF + tid], deg = smi[O_OFF + tid + 1] - o;
        float m = -1e30f;
        for (int i = 0; i < deg; i++) m = fmaxf(m, sm[O_E2 + smi[O_CSR + o + i]]);
        float s = 0.f;
        for (int i = 0; i < deg; i++) s += expf(sm[O_E2 + smi[O_CSR + o + i]] - m);
        sm[O_M2 + tid]  = m;
        sm[O_IS2 + tid] = 1.f/(s + 1e-16f);
    }
    __syncthreads();
    for (int k = tid; k < ET; k += NTH) {
        int d = smi[O_DST + k];
        sm[O_AL2 + k] = expf(sm[O_E2 + k] - sm[O_M2 + d]) * sm[O_IS2 + d];
    }
    __syncthreads();
    {   // aggregation + bias + elu -> g2   (thread = dst, 8 channels)
        int dst = tid >> 3, cc = (tid & 7) * 8;
        int o = smi[O_OFF + dst], deg = smi[O_OFF + dst + 1] - o;
        float acc[8];
        #pragma unroll
        for (int i = 0; i < 8; i++) acc[i] = 0.f;
        for (int i = 0; i < deg; i++) {
            int k = smi[O_CSR + o + i];
            float a = sm[O_AL2 + k];
            const float* hr = &sm[O_H2 + smi[O_SRC + k]*HS + cc];
            #pragma unroll
            for (int c = 0; c < 8; c++) acc[c] = fmaf(a, hr[c], acc[c]);
        }
        float* g = &sm[O_G2 + dst*HS + cc];
        #pragma unroll
        for (int c = 0; c < 8; c++) g[c] = eluf_(acc[c] + b2[cc + c]);
    }
    __syncthreads();

    // ---------------- Phase 7: LayerNorm (in place, thread per node)
    if (tid < NN) {
        float* r = &sm[O_G2 + tid*HS];
        float mu = 0.f;
        #pragma unroll
        for (int c = 0; c < HID; c++) mu += r[c];
        mu *= (1.f/HID);
        float var = 0.f;
        #pragma unroll
        for (int c = 0; c < HID; c++) { float d = r[c] - mu; var = fmaf(d, d, var); }
        var *= (1.f/HID);
        float is = rsqrtf(var + 1e-5f);
        #pragma unroll
        for (int c = 0; c < HID; c++) r[c] = (r[c] - mu)*is*gamma[c] + beta[c];
    }
    __syncthreads();

    // ---------------- Phase 8: xi1[t][j] = bi1 + sum_n hln[n][t] * Wi1[j][n]
    for (int o = tid; o < HID*192; o += NTH) {
        int j = o >> 6, tt = o & 63;
        float acc = bi1[j];
        #pragma unroll
        for (int n = 0; n < NN; n++)
            acc = fmaf(Wi1[j*NN + n], sm[O_G2 + n*HS + tt], acc);
        sm[O_XI + tt*XIS + j] = acc;
    }
    // Wh1 rows into registers (thread j owns gate row j)
    float wh[HID]; float bh = 0.f;
    if (tid < 192) {
        bh = bh1[tid];
        #pragma unroll
        for (int k = 0; k < HID; k++) wh[k] = Wh1[tid*HID + k];
    }
    if (tid < HID) sm[O_HSM + tid] = 0.f;
    __syncthreads();

    // ---------------- Phase 9: GRU1 recurrence (64 steps), store ys
    for (int t = 0; t < HID; t++) {
        if (tid < 192) {
            float g = bh;
            #pragma unroll
            for (int k = 0; k < HID; k++) g = fmaf(wh[k], sm[O_HSM + k], g);
            sm[O_GH + tid] = g;
        }
        __syncthreads();
        if (tid < HID) {
            const float* xr = &sm[O_XI + t*XIS];
            float r  = sigmf_(xr[tid]       + sm[O_GH + tid]);
            float z  = sigmf_(xr[64 + tid]  + sm[O_GH + 64 + tid]);
            float nv = tanhf(fmaf(r, sm[O_GH + 128 + tid], xr[128 + tid]));
            float hn = (1.f - z)*nv + z*sm[O_HSM + tid];
            sm[O_HSM + tid]        = hn;
            sm[O_YS + t*YSS + tid] = hn;
        }
        __syncthreads();
    }

    // ---------------- Phase 10: xi2 from ys (xi1 buffer is dead)
    for (int o = tid; o < HID*192; o += NTH) {
        int j = o >> 6, tt = o & 63;
        float acc = bi2[j];
        #pragma unroll
        for (int k = 0; k < HID; k++)
            acc = fmaf(Wi2[j*HID + k], sm[O_YS + tt*YSS + k], acc);
        sm[O_XI + tt*XIS + j] = acc;
    }
    if (tid < 192) {
        bh = bh2[tid];
        #pragma unroll
        for (int k = 0; k < HID; k++) wh[k] = Wh2[tid*HID + k];
    }
    if (tid < HID) sm[O_HSM + tid] = 0.f;
    __syncthreads();

    // ---------------- Phase 11: GRU2 recurrence (only final h needed)
    for (int t = 0; t < HID; t++) {
        if (tid < 192) {
            float g = bh;
            #pragma unroll
            for (int k = 0; k < HID; k++) g = fmaf(wh[k], sm[O_HSM + k], g);
            sm[O_GH + tid] = g;
        }
        __syncthreads();
        if (tid < HID) {
            const float* xr = &sm[O_XI + t*XIS];
            float r  = sigmf_(xr[tid]       + sm[O_GH + tid]);
            float z  = sigmf_(xr[64 + tid]  + sm[O_GH + 64 + tid]);
            float nv = tanhf(fmaf(r, sm[O_GH + 128 + tid], xr[128 + tid]));
            sm[O_HSM + tid] = (1.f - z)*nv + z*sm[O_HSM + tid];
        }
        __syncthreads();
    }

    // ---------------- Phase 12: final linear  out[b] = h_last @ Wf^T + bf
    if (tid < 9) {
        float acc = bf[tid];
        #pragma unroll
        for (int k = 0; k < HID; k++)
            acc = fmaf(sm[O_HSM + k], Wf[tid*HID + k], acc);
        out[b*9 + tid] = acc;
    }
}

extern "C" void kernel_launch(void* const* d_in, const int* in_sizes, int n_in,
                              void* d_out, int out_size) {
    (void)in_sizes; (void)n_in; (void)out_size;
    const float* x    = (const float*)d_in[0];
    const int*   ei   = (const int*)  d_in[1];
    const float* W1   = (const float*)d_in[2];
    const float* aS1  = (const float*)d_in[3];
    const float* aD1  = (const float*)d_in[4];
    const float* b1   = (const float*)d_in[5];
    const float* W2   = (const float*)d_in[6];
    const float* aS2  = (const float*)d_in[7];
    const float* aD2  = (const float*)d_in[8];
    const float* b2   = (const float*)d_in[9];
    const float* gam  = (const float*)d_in[10];
    const float* bet  = (const float*)d_in[11];
    const float* Wi1  = (const float*)d_in[12];
    const float* Wh1  = (const float*)d_in[13];
    const float* bi1  = (const float*)d_in[14];
    const float* bh1  = (const float*)d_in[15];
    const float* Wi2  = (const float*)d_in[16];
    const float* Wh2  = (const float*)d_in[17];
    const float* bi2  = (const float*)d_in[18];
    const float* bh2  = (const float*)d_in[19];
    const float* Wf   = (const float*)d_in[20];
    const float* bf   = (const float*)d_in[21];
    float* out = (float*)d_out;

    size_t smem = (size_t)SMEM_FLOATS * sizeof(float);
    cudaFuncSetAttribute(fused_gatgru_kernel,
                         cudaFuncAttributeMaxDynamicSharedMemorySize, (int)smem);
    fused_gatgru_kernel<<<512, NTH, smem>>>(
        x, ei, W1, aS1, aD1, b1, W2, aS2, aD2, b2, gam, bet,
        Wi1, Wh1, bi1, bh1, Wi2, Wh2, bi2, bh2, Wf, bf, out);
}

// round 2
// speedup vs baseline: 1.1667x; 1.1667x over previous
#include <cuda_runtime.h>
#include <math.h>

#define NN     32
#define TIN    12
#define HID    64
#define HEADS  8
#define HH     512
#define EPB    256
#define ET     288
#define E_     131072
#define NTH    256
#define RS     68    // h1 row stride (row = n*8+h), 16B aligned
#define H2S    68
#define HLNTS  36
#define XIS    196
#define YSS    68

// shared memory offsets (floats)
#define O_H1    0        // 256*68 = 17408 (GAT)  | GRU: XI(64*196=12544) + YS
#define O_XI    0
#define O_YS    12544    // 64*68 = 4352 -> ends 16896
#define O_X     17408    // 384 (dead after ph1)
#define O_ES2   17408    // 32  (phase 6)
#define O_ED2   17440    // 32
#define O_M2    17472    // 32
#define O_IS2   17504    // 32
#define O_AL2   17536    // 288
#define O_ES    17792    // 256 (dead after ph3)
#define O_E2    17824    // 288 (phase 6)
#define O_ED    18048    // 256 (dead after ph3)
#define O_E     18304    // 2304 (p; dead after ph4)
#define O_HLNT  18304    // 64*36 = 2304 (phase 7+)
#define O_SRC   20608    // 288 int
#define O_DST   20896    // 288 int
#define O_CNT   21184    // 32 int
#define O_OFF   21216    // 33 int
#define O_SLOT  21249    // 288 int
#define O_CSR   21537    // 288 int -> 21825
#define O_H2    21828    // 32*68 = 2176 -> 24004
#define O_G2    24004    // 32*68 = 2176 -> 26180 (dead after ph7)
#define O_HSM   24004    // 64 (GRU)
#define O_GH    24068    // 192
#define SMEM_FLOATS 26180   // 104720 B -> 2 CTAs/SM

__device__ __forceinline__ float sigmf_(float x){ return 1.0f/(1.0f+expf(-x)); }
__device__ __forceinline__ float eluf_(float x){ return x>0.f ? x : expm1f(x); }
__device__ __forceinline__ float lreluf_(float x){ return x>0.f ? x : 0.2f*x; }

__global__ void __launch_bounds__(NTH, 2) fused_gatgru_kernel(
    const float* __restrict__ x,   const int*   __restrict__ ei,
    const float* __restrict__ W1,  const float* __restrict__ aS1,
    const float* __restrict__ aD1, const float* __restrict__ b1,
    const float* __restrict__ W2,  const float* __restrict__ aS2,
    const float* __restrict__ aD2, const float* __restrict__ b2,
    const float* __restrict__ gamma, const float* __restrict__ beta,
    const float* __restrict__ Wi1, const float* __restrict__ Wh1,
    const float* __restrict__ bi1, const float* __restrict__ bh1,
    const float* __restrict__ Wi2, const float* __restrict__ Wh2,
    const float* __restrict__ bi2, const float* __restrict__ bh2,
    const float* __restrict__ Wf,  const float* __restrict__ bf,
    float* __restrict__ out)
{
    extern __shared__ float sm[];
    int* smi = (int*)sm;
    const int tid = threadIdx.x;
    const int b   = blockIdx.x;

    // ---------------- Phase 0: load x (float4) + edge list, zero counters
    {
        const float4* xg = (const float4*)(x + b*NN*TIN);
        float4* xs = (float4*)&sm[O_X];
        if (tid < 96) xs[tid] = xg[tid];
    }
    for (int k = tid; k < ET; k += NTH) {
        int s, d;
        if (k < EPB) { s = ei[b*EPB + k] - b*NN; d = ei[E_ + b*EPB + k] - b*NN; }
        else         { s = d = k - EPB; }
        smi[O_SRC + k] = s; smi[O_DST + k] = d;
    }
    if (tid < NN) smi[O_CNT + tid] = 0;
    __syncthreads();

    // ---------------- Phase 1: h1 = x @ W1 (rows (n,h), stride 68) + CSR counting
    for (int jj = 0; jj < 2; jj++) {
        int j = tid + jj*NTH;
        int h = j >> 6, c = j & 63;
        float w[TIN];
        #pragma unroll
        for (int k = 0; k < TIN; k++) w[k] = W1[k*HH + j];
        for (int n = 0; n < NN; n++) {
            const float4* xr = (const float4*)&sm[O_X + n*TIN];
            float4 x0 = xr[0], x1 = xr[1], x2 = xr[2];
            float a0 = x0.x*w[0] + x0.z*w[2];
            float a1 = x0.y*w[1] + x0.w*w[3];
            a0 = fmaf(x1.x, w[4], a0); a1 = fmaf(x1.y, w[5], a1);
            a0 = fmaf(x1.z, w[6], a0); a1 = fmaf(x1.w, w[7], a1);
            a0 = fmaf(x2.x, w[8], a0); a1 = fmaf(x2.y, w[9], a1);
            a0 = fmaf(x2.z, w[10], a0); a1 = fmaf(x2.w, w[11], a1);
            sm[O_H1 + (n*8 + h)*RS + c] = a0 + a1;
        }
    }
    for (int k = tid; k < ET; k += NTH)
        smi[O_SLOT + k] = atomicAdd(&smi[O_CNT + smi[O_DST + k]], 1);
    __syncthreads();

    // ---------------- Phase 2: es/ed dots (float4) + CSR prefix sum
    {
        int n = tid >> 3, h = tid & 7;
        const float4* hr = (const float4*)&sm[O_H1 + (n*8 + h)*RS];
        const float4* as = (const float4*)(aS1 + h*HID);
        const float4* ad = (const float4*)(aD1 + h*HID);
        float e0 = 0.f, e1 = 0.f, d0 = 0.f, d1 = 0.f;
        #pragma unroll
        for (int kk = 0; kk < 16; kk++) {
            float4 v = hr[kk], a = as[kk], dd = ad[kk];
            e0 = fmaf(v.x, a.x, e0); e1 = fmaf(v.y, a.y, e1);
            e0 = fmaf(v.z, a.z, e0); e1 = fmaf(v.w, a.w, e1);
            d0 = fmaf(v.x, dd.x, d0); d1 = fmaf(v.y, dd.y, d1);
            d0 = fmaf(v.z, dd.z, d0); d1 = fmaf(v.w, dd.w, d1);
        }
        sm[O_ES + n*8 + h] = e0 + e1;
        sm[O_ED + n*8 + h] = d0 + d1;
    }
    if (tid == 0) {
        int acc = 0;
        for (int d = 0; d < NN; d++) { smi[O_OFF + d] = acc; acc += smi[O_CNT + d]; }
        smi[O_OFF + NN] = acc;
    }
    __syncthreads();

    // ---------------- Phase 3: edge scores (8 heads per edge, float4) + CSR scatter
    for (int k = tid; k < ET; k += NTH) {
        int s = smi[O_SRC + k], d = smi[O_DST + k];
        const float4* es = (const float4*)&sm[O_ES + s*8];
        const float4* ed = (const float4*)&sm[O_ED + d*8];
        float4* eo = (float4*)&sm[O_E + k*8];
        float4 a0 = es[0], a1 = es[1], b0 = ed[0], b1 = ed[1];
        float4 r0, r1;
        r0.x = lreluf_(a0.x + b0.x); r0.y = lreluf_(a0.y + b0.y);
        r0.z = lreluf_(a0.z + b0.z); r0.w = lreluf_(a0.w + b0.w);
        r1.x = lreluf_(a1.x + b1.x); r1.y = lreluf_(a1.y + b1.y);
        r1.z = lreluf_(a1.z + b1.z); r1.w = lreluf_(a1.w + b1.w);
        eo[0] = r0; eo[1] = r1;
    }
    for (int k = tid; k < ET; k += NTH)
        smi[O_CSR + smi[O_OFF + smi[O_DST + k]] + smi[O_SLOT + k]] = k;
    __syncthreads();

    // ---------------- Phase 4: GAT1 softmax + aggregation (thread = dst,head; float4)
    {
        int dst = tid >> 3, h = tid & 7;
        int o   = smi[O_OFF + dst], deg = smi[O_OFF + dst + 1] - o;
        float m = -1e30f;
        for (int i = 0; i < deg; i++)
            m = fmaxf(m, sm[O_E + smi[O_CSR + o + i]*8 + h]);
        float s = 0.f;
        for (int i = 0; i < deg; i++) {
            int k = smi[O_CSR + o + i];
            float p = expf(sm[O_E + k*8 + h] - m);
            sm[O_E + k*8 + h] = p;
            s += p;
        }
        float inv = 1.f/(s + 1e-16f);
        float4 acc[16];
        #pragma unroll
        for (int j = 0; j < 16; j++) acc[j] = make_float4(0.f,0.f,0.f,0.f);
        for (int i = 0; i < deg; i++) {
            int k = smi[O_CSR + o + i];
            float p = sm[O_E + k*8 + h];
            const float4* hr = (const float4*)&sm[O_H1 + (smi[O_SRC + k]*8 + h)*RS];
            #pragma unroll
            for (int j = 0; j < 16; j++) {
                float4 v = hr[j];
                acc[j].x = fmaf(p, v.x, acc[j].x);
                acc[j].y = fmaf(p, v.y, acc[j].y);
                acc[j].z = fmaf(p, v.z, acc[j].z);
                acc[j].w = fmaf(p, v.w, acc[j].w);
            }
        }
        __syncthreads();   // finish all h1 reads before in-place overwrite
        float4* orow = (float4*)&sm[O_H1 + (dst*8 + h)*RS];
        const float4* bb = (const float4*)(b1 + h*HID);
        #pragma unroll
        for (int j = 0; j < 16; j++) {
            float4 bv = bb[j], r;
            r.x = eluf_(fmaf(acc[j].x, inv, bv.x));
            r.y = eluf_(fmaf(acc[j].y, inv, bv.y));
            r.z = eluf_(fmaf(acc[j].z, inv, bv.z));
            r.w = eluf_(fmaf(acc[j].w, inv, bv.w));
            orow[j] = r;
        }
    }
    __syncthreads();

    // ---------------- Phase 5: h2 = out1 @ W2 (32x512 @ 512x64), float4 over k
    {
        int c = tid & 63, grp = tid >> 6;   // nodes grp*8 .. grp*8+7
        float acc[8];
        #pragma unroll
        for (int i = 0; i < 8; i++) acc[i] = 0.f;
        for (int hd = 0; hd < 8; hd++) {
            const float* w2p = W2 + hd*64*HID + c;
            #pragma unroll 4
            for (int kc = 0; kc < 64; kc += 4) {
                float w0 = w2p[(kc+0)*HID], w1 = w2p[(kc+1)*HID];
                float w2v = w2p[(kc+2)*HID], w3 = w2p[(kc+3)*HID];
                #pragma unroll
                for (int i = 0; i < 8; i++) {
                    float4 v = *(const float4*)&sm[O_H1 + ((grp*8+i)*8 + hd)*RS + kc];
                    float t0 = fmaf(v.x, w0, v.y*w1);
                    float t1 = fmaf(v.z, w2v, v.w*w3);
                    acc[i] += t0 + t1;
                }
            }
        }
        #pragma unroll
        for (int i = 0; i < 8; i++) sm[O_H2 + (grp*8+i)*H2S + c] = acc[i];
    }
    __syncthreads();

    // ---------------- Phase 6: GAT2 attention
    if (tid < 64) {
        int n = tid & 31;
        const float4* a  = (const float4*)((tid < 32) ? aS2 : aD2);
        const float4* hr = (const float4*)&sm[O_H2 + n*H2S];
        float a0 = 0.f, a1 = 0.f;
        #pragma unroll
        for (int kk = 0; kk < 16; kk++) {
            float4 v = hr[kk], w = a[kk];
            a0 = fmaf(v.x, w.x, a0); a1 = fmaf(v.y, w.y, a1);
            a0 = fmaf(v.z, w.z, a0); a1 = fmaf(v.w, w.w, a1);
        }
        sm[(tid < 32 ? O_ES2 : O_ED2) + n] = a0 + a1;
    }
    __syncthreads();
    for (int k = tid; k < ET; k += NTH)
        sm[O_E2 + k] = lreluf_(sm[O_ES2 + smi[O_SRC + k]] + sm[O_ED2 + smi[O_DST + k]]);
    __syncthreads();
    if (tid < NN) {
        int o = smi[O_OFF + tid], deg = smi[O_OFF + tid + 1] - o;
        float m = -1e30f;
        for (int i = 0; i < deg; i++) m = fmaxf(m, sm[O_E2 + smi[O_CSR + o + i]]);
        float s = 0.f;
        for (int i = 0; i < deg; i++) s += expf(sm[O_E2 + smi[O_CSR + o + i]] - m);
        sm[O_M2 + tid]  = m;
        sm[O_IS2 + tid] = 1.f/(s + 1e-16f);
    }
    __syncthreads();
    for (int k = tid; k < ET; k += NTH) {
        int d = smi[O_DST + k];
        sm[O_AL2 + k] = expf(sm[O_E2 + k] - sm[O_M2 + d]) * sm[O_IS2 + d];
    }
    __syncthreads();
    {   // aggregation + bias + elu -> g2 (thread = dst, 8 channels via 2 float4)
        int dst = tid >> 3, cc = (tid & 7) * 8;
        int o = smi[O_OFF + dst], deg = smi[O_OFF + dst + 1] - o;
        float4 a0 = make_float4(0.f,0.f,0.f,0.f), a1 = a0;
        for (int i = 0; i < deg; i++) {
            int k = smi[O_CSR + o + i];
            float al = sm[O_AL2 + k];
            const float4* hr = (const float4*)&sm[O_H2 + smi[O_SRC + k]*H2S + cc];
            float4 v0 = hr[0], v1 = hr[1];
            a0.x = fmaf(al, v0.x, a0.x); a0.y = fmaf(al, v0.y, a0.y);
            a0.z = fmaf(al, v0.z, a0.z); a0.w = fmaf(al, v0.w, a0.w);
            a1.x = fmaf(al, v1.x, a1.x); a1.y = fmaf(al, v1.y, a1.y);
            a1.z = fmaf(al, v1.z, a1.z); a1.w = fmaf(al, v1.w, a1.w);
        }
        const float4* bb = (const float4*)(b2 + cc);
        float4 b0 = bb[0], b1v = bb[1], r0, r1;
        r0.x = eluf_(a0.x + b0.x); r0.y = eluf_(a0.y + b0.y);
        r0.z = eluf_(a0.z + b0.z); r0.w = eluf_(a0.w + b0.w);
        r1.x = eluf_(a1.x + b1v.x); r1.y = eluf_(a1.y + b1v.y);
        r1.z = eluf_(a1.z + b1v.z); r1.w = eluf_(a1.w + b1v.w);
        float4* g = (float4*)&sm[O_G2 + dst*H2S + cc];
        g[0] = r0; g[1] = r1;
    }
    __syncthreads();

    // ---------------- Phase 7: LayerNorm + transpose -> hlnT[t][n]
    if (tid < NN) {
        const float4* r4 = (const float4*)&sm[O_G2 + tid*H2S];
        float4 row[16];
        float mu = 0.f;
        #pragma unroll
        for (int kk = 0; kk < 16; kk++) {
            row[kk] = r4[kk];
            mu += (row[kk].x + row[kk].y) + (row[kk].z + row[kk].w);
        }
        mu *= (1.f/HID);
        float var = 0.f;
        #pragma unroll
        for (int kk = 0; kk < 16; kk++) {
            float dx = row[kk].x-mu, dy = row[kk].y-mu, dz = row[kk].z-mu, dw = row[kk].w-mu;
            var += fmaf(dx,dx, dy*dy) + fmaf(dz,dz, dw*dw);
        }
        var *= (1.f/HID);
        float is = rsqrtf(var + 1e-5f);
        #pragma unroll
        for (int kk = 0; kk < 16; kk++) {
            int t = kk*4;
            sm[O_HLNT + (t+0)*HLNTS + tid] = (row[kk].x - mu)*is*gamma[t+0] + beta[t+0];
            sm[O_HLNT + (t+1)*HLNTS + tid] = (row[kk].y - mu)*is*gamma[t+1] + beta[t+1];
            sm[O_HLNT + (t+2)*HLNTS + tid] = (row[kk].z - mu)*is*gamma[t+2] + beta[t+2];
            sm[O_HLNT + (t+3)*HLNTS + tid] = (row[kk].w - mu)*is*gamma[t+3] + beta[t+3];
        }
    }
    __syncthreads();

    // ---------------- Phase 8: xi1[t][j] = bi1[j] + sum_n Wi1[j][n] * hlnT[t][n]
    for (int o = tid; o < HID*192; o += NTH) {
        int j = o >> 6, t = o & 63;
        const float4* wr = (const float4*)(Wi1 + j*NN);
        const float4* hr = (const float4*)&sm[O_HLNT + t*HLNTS];
        float a0 = 0.f, a1 = 0.f, a2 = 0.f, a3 = 0.f;
        #pragma unroll
        for (int kk = 0; kk < 8; kk++) {
            float4 w = wr[kk], v = hr[kk];
            a0 = fmaf(w.x, v.x, a0); a1 = fmaf(w.y, v.y, a1);
            a2 = fmaf(w.z, v.z, a2); a3 = fmaf(w.w, v.w, a3);
        }
        sm[O_XI + t*XIS + j] = bi1[j] + ((a0+a1) + (a2+a3));
    }
    // Wh1 rows into registers
    float4 wh4[16]; float bh = 0.f;
    if (tid < 192) {
        bh = bh1[tid];
        const float4* w = (const float4*)(Wh1 + tid*HID);
        #pragma unroll
        for (int kk = 0; kk < 16; kk++) wh4[kk] = w[kk];
    }
    if (tid < HID) sm[O_HSM + tid] = 0.f;
    __syncthreads();

    // ---------------- Phase 9: GRU1 recurrence (64 steps), store ys
    for (int t = 0; t < HID; t++) {
        if (tid < 192) {
            const float4* h4 = (const float4*)&sm[O_HSM];
            float a0 = bh, a1 = 0.f, a2 = 0.f, a3 = 0.f;
            #pragma unroll
            for (int kk = 0; kk < 16; kk++) {
                float4 hv = h4[kk];
                a0 = fmaf(wh4[kk].x, hv.x, a0); a1 = fmaf(wh4[kk].y, hv.y, a1);
                a2 = fmaf(wh4[kk].z, hv.z, a2); a3 = fmaf(wh4[kk].w, hv.w, a3);
            }
            sm[O_GH + tid] = (a0+a1) + (a2+a3);
        }
        __syncthreads();
        if (tid < HID) {
            const float* xr = &sm[O_XI + t*XIS];
            float r  = sigmf_(xr[tid]       + sm[O_GH + tid]);
            float z  = sigmf_(xr[64 + tid]  + sm[O_GH + 64 + tid]);
            float nv = tanhf(fmaf(r, sm[O_GH + 128 + tid], xr[128 + tid]));
            float hn = (1.f - z)*nv + z*sm[O_HSM + tid];
            sm[O_HSM + tid]        = hn;
            sm[O_YS + t*YSS + tid] = hn;
        }
        __syncthreads();
    }

    // ---------------- Phase 10: xi2[t][j] = bi2[j] + sum_k Wi2[j][k] * ys[t][k]
    for (int o = tid; o < HID*192; o += NTH) {
        int j = o >> 6, t = o & 63;
        const float4* wr = (const float4*)(Wi2 + j*HID);
        const float4* yr = (const float4*)&sm[O_YS + t*YSS];
        float a0 = 0.f, a1 = 0.f, a2 = 0.f, a3 = 0.f;
        #pragma unroll
        for (int kk = 0; kk < 16; kk++) {
            float4 w = wr[kk], v = yr[kk];
            a0 = fmaf(w.x, v.x, a0); a1 = fmaf(w.y, v.y, a1);
            a2 = fmaf(w.z, v.z, a2); a3 = fmaf(w.w, v.w, a3);
        }
        sm[O_XI + t*XIS + j] = bi2[j] + ((a0+a1) + (a2+a3));
    }
    if (tid < 192) {
        bh = bh2[tid];
        const float4* w = (const float4*)(Wh2 + tid*HID);
        #pragma unroll
        for (int kk = 0; kk < 16; kk++) wh4[kk] = w[kk];
    }
    if (tid < HID) sm[O_HSM + tid] = 0.f;
    __syncthreads();

    // ---------------- Phase 11: GRU2 recurrence (only final h needed)
    for (int t = 0; t < HID; t++) {
        if (tid < 192) {
            const float4* h4 = (const float4*)&sm[O_HSM];
            float a0 = bh, a1 = 0.f, a2 = 0.f, a3 = 0.f;
            #pragma unroll
            for (int kk = 0; kk < 16; kk++) {
                float4 hv = h4[kk];
                a0 = fmaf(wh4[kk].x, hv.x, a0); a1 = fmaf(wh4[kk].y, hv.y, a1);
                a2 = fmaf(wh4[kk].z, hv.z, a2); a3 = fmaf(wh4[kk].w, hv.w, a3);
            }
            sm[O_GH + tid] = (a0+a1) + (a2+a3);
        }
        __syncthreads();
        if (tid < HID) {
            const float* xr = &sm[O_XI + t*XIS];
            float r  = sigmf_(xr[tid]       + sm[O_GH + tid]);
            float z  = sigmf_(xr[64 + tid]  + sm[O_GH + 64 + tid]);
            float nv = tanhf(fmaf(r, sm[O_GH + 128 + tid], xr[128 + tid]));
            sm[O_HSM + tid] = (1.f - z)*nv + z*sm[O_HSM + tid];
        }
        __syncthreads();
    }

    // ---------------- Phase 12: final linear
    if (tid < 9) {
        const float4* w = (const float4*)(Wf + tid*HID);
        const float4* h4 = (const float4*)&sm[O_HSM];
        float a0 = bf[tid], a1 = 0.f, a2 = 0.f, a3 = 0.f;
        #pragma unroll
        for (int kk = 0; kk < 16; kk++) {
            float4 wv = w[kk], hv = h4[kk];
            a0 = fmaf(wv.x, hv.x, a0); a1 = fmaf(wv.y, hv.y, a1);
            a2 = fmaf(wv.z, hv.z, a2); a3 = fmaf(wv.w, hv.w, a3);
        }
        out[b*9 + tid] = (a0+a1) + (a2+a3);
    }
}

extern "C" void kernel_launch(void* const* d_in, const int* in_sizes, int n_in,
                              void* d_out, int out_size) {
    (void)in_sizes; (void)n_in; (void)out_size;
    const float* x    = (const float*)d_in[0];
    const int*   ei   = (const int*)  d_in[1];
    const float* W1   = (const float*)d_in[2];
    const float* aS1  = (const float*)d_in[3];
    const float* aD1  = (const float*)d_in[4];
    const float* b1   = (const float*)d_in[5];
    const float* W2   = (const float*)d_in[6];
    const float* aS2  = (const float*)d_in[7];
    const float* aD2  = (const float*)d_in[8];
    const float* b2   = (const float*)d_in[9];
    const float* gam  = (const float*)d_in[10];
    const float* bet  = (const float*)d_in[11];
    const float* Wi1  = (const float*)d_in[12];
    const float* Wh1  = (const float*)d_in[13];
    const float* bi1  = (const float*)d_in[14];
    const float* bh1  = (const float*)d_in[15];
    const float* Wi2  = (const float*)d_in[16];
    const float* Wh2  = (const float*)d_in[17];
    const float* bi2  = (const float*)d_in[18];
    const float* bh2  = (const float*)d_in[19];
    const float* Wf   = (const float*)d_in[20];
    const float* bf   = (const float*)d_in[21];
    float* out = (float*)d_out;

    size_t smem = (size_t)SMEM_FLOATS * sizeof(float);
    cudaFuncSetAttribute(fused_gatgru_kernel,
                         cudaFuncAttributeMaxDynamicSharedMemorySize, (int)smem);
    fused_gatgru_kernel<<<512, NTH, smem>>>(
        x, ei, W1, aS1, aD1, b1, W2, aS2, aD2, b2, gam, bet,
        Wi1, Wh1, bi1, bh1, Wi2, Wh2, bi2, bh2, Wf, bf, out);
}